// round 2
// baseline (speedup 1.0000x reference)
#include <cuda_runtime.h>

// ---------------------------------------------------------------------------
// NeuralODESIR: fused RK4 + 4-layer tanh MLP, fp32, packed f32x2 FMA microkernel
// One CTA owns 128 batch rows for all 100 steps. Weights + activations in smem.
// ---------------------------------------------------------------------------

#define SBUF 132   // activation buffer row stride (floats); 132 % 32 = 4 -> no bank aliasing

__device__ __forceinline__ unsigned long long fma2v(unsigned long long a,
                                                    unsigned long long b,
                                                    unsigned long long c) {
    unsigned long long d;
    asm("fma.rn.f32x2 %0, %1, %2, %3;" : "=l"(d) : "l"(a), "l"(b), "l"(c));
    return d;
}
__device__ __forceinline__ unsigned long long dup2(float x) {
    unsigned long long r;
    asm("mov.b64 %0, {%1, %1};" : "=l"(r) : "f"(x));
    return r;
}
__device__ __forceinline__ void unpack2(unsigned long long v, float& lo, float& hi) {
    asm("mov.b64 {%0, %1}, %2;" : "=f"(lo), "=f"(hi) : "l"(v));
}

// tanh(x) = 1 - 2/(exp(2x)+1).  __expf: MUFU.EX2-based, ~2ulp. Handles +-inf ends.
__device__ __forceinline__ float tanh_fast(float x) {
    float e = __expf(2.0f * x);
    return 1.0f - __fdividef(2.0f, e + 1.0f);
}

// C[N][128] = tanh(A[K][128]^T-ish GEMM): C[c][r] = tanh(bias[c] + sum_k A[k][r]*W[k][c])
// A, C column-major tiles with row stride SBUF. 256 threads: tx=t&15 (cols, interleaved
// by 16), ty=t>>4 (8-row groups). Accumulators are packed f32x2 over row pairs.
template <int K, int N, int NR>
__device__ __forceinline__ void gemm_tanh_layer(const float* __restrict__ As,
                                                const float* __restrict__ Ws,
                                                const float* __restrict__ Bs,
                                                float* __restrict__ Cs, int t) {
    const int tx = t & 15;
    const int ty = t >> 4;
    const int r0 = ty * 8;

    unsigned long long acc[NR][4];
#pragma unroll
    for (int j = 0; j < NR; ++j) {
        unsigned long long b = dup2(Bs[tx + 16 * j]);
#pragma unroll
        for (int p = 0; p < 4; ++p) acc[j][p] = b;
    }

#pragma unroll 4
    for (int k = 0; k < K; ++k) {
        const ulonglong2* Ap = reinterpret_cast<const ulonglong2*>(As + k * SBUF + r0);
        ulonglong2 a01 = Ap[0];
        ulonglong2 a23 = Ap[1];
        const float* Wp = Ws + k * N + tx;
#pragma unroll
        for (int j = 0; j < NR; ++j) {
            unsigned long long w = dup2(Wp[16 * j]);
            acc[j][0] = fma2v(a01.x, w, acc[j][0]);
            acc[j][1] = fma2v(a01.y, w, acc[j][1]);
            acc[j][2] = fma2v(a23.x, w, acc[j][2]);
            acc[j][3] = fma2v(a23.y, w, acc[j][3]);
        }
    }

#pragma unroll
    for (int j = 0; j < NR; ++j) {
        float o[8];
#pragma unroll
        for (int p = 0; p < 4; ++p) {
            float lo, hi;
            unpack2(acc[j][p], lo, hi);
            o[2 * p]     = tanh_fast(lo);
            o[2 * p + 1] = tanh_fast(hi);
        }
        float4* dst = reinterpret_cast<float4*>(Cs + (tx + 16 * j) * SBUF + r0);
        dst[0] = make_float4(o[0], o[1], o[2], o[3]);
        dst[1] = make_float4(o[4], o[5], o[6], o[7]);
    }
}

// smem plan (floats)
#define OFF_W1   0
#define OFF_B1   (OFF_W1 + 320)
#define OFF_W2   (OFF_B1 + 64)
#define OFF_B2   (OFF_W2 + 8192)
#define OFF_W3   (OFF_B2 + 128)
#define OFF_B3   (OFF_W3 + 8192)
#define OFF_W4   (OFF_B3 + 64)
#define OFF_B4   (OFF_W4 + 192)
#define OFF_TS   (OFF_B4 + 4)
#define OFF_YIN  (OFF_TS + 128)
#define OFF_BUFA (OFF_YIN + 640)          // 64 x SBUF
#define OFF_BUFB (OFF_BUFA + 64 * SBUF)   // 128 x SBUF
#define SM_FLOATS (OFF_BUFB + 128 * SBUF)

__global__ void __launch_bounds__(256, 1)
node_sir_kernel(const float* __restrict__ y0, const float* __restrict__ t_span,
                const float* __restrict__ beta, const float* __restrict__ gamma_,
                const float* __restrict__ W1, const float* __restrict__ b1,
                const float* __restrict__ W2, const float* __restrict__ b2,
                const float* __restrict__ W3, const float* __restrict__ b3,
                const float* __restrict__ W4, const float* __restrict__ b4,
                float* __restrict__ out, int B, int T) {
    extern __shared__ float sm[];
    float* W1s  = sm + OFF_W1;
    float* b1s  = sm + OFF_B1;
    float* W2s  = sm + OFF_W2;
    float* b2s  = sm + OFF_B2;
    float* W3s  = sm + OFF_W3;
    float* b3s  = sm + OFF_B3;
    float* W4s  = sm + OFF_W4;
    float* b4s  = sm + OFF_B4;
    float* tss  = sm + OFF_TS;
    float* yin  = sm + OFF_YIN;
    float* bufA = sm + OFF_BUFA;
    float* bufB = sm + OFF_BUFB;

    const int t = threadIdx.x;

    for (int i = t; i < 320; i += 256) W1s[i] = W1[i];
    for (int i = t; i < 64; i += 256) b1s[i] = b1[i];
    for (int i = t; i < 8192; i += 256) W2s[i] = W2[i];
    for (int i = t; i < 128; i += 256) b2s[i] = b2[i];
    for (int i = t; i < 8192; i += 256) W3s[i] = W3[i];
    for (int i = t; i < 64; i += 256) b3s[i] = b3[i];
    for (int i = t; i < 192; i += 256) W4s[i] = W4[i];
    if (t < 3) b4s[t] = b4[t];
    for (int i = t; i < T && i < 128; i += 256) tss[i] = t_span[i];

    const int b0 = blockIdx.x * 128;
    float bS = 0.f, bI = 0.f, bR = 0.f;   // base state (valid for t<128)
    float aS = 0.f, aI = 0.f, aR = 0.f;   // RK4 accumulator

    if (t < 128) {
        int gr = b0 + t;
        bS = y0[gr * 3 + 0];
        bI = y0[gr * 3 + 1];
        bR = y0[gr * 3 + 2];
        yin[t]         = bS;
        yin[128 + t]   = bI;
        yin[256 + t]   = bR;
        yin[384 + t]   = beta[gr];
        yin[512 + t]   = gamma_[gr];
        // output at step 0: softmax(y0)
        float m  = fmaxf(bS, fmaxf(bI, bR));
        float e0 = __expf(bS - m), e1 = __expf(bI - m), e2 = __expf(bR - m);
        float inv = __fdividef(1.0f, e0 + e1 + e2);
        size_t o = (size_t)gr * 3;
        out[o] = e0 * inv; out[o + 1] = e1 * inv; out[o + 2] = e2 * inv;
    }
    __syncthreads();

    for (int s = 0; s < T - 1; ++s) {
        float dt = tss[s + 1] - tss[s];
        for (int sub = 0; sub < 4; ++sub) {
            // ---- Layer 1: [128,5] @ [5,64] -> bufA (col-major [64][SBUF]) ----
            for (int idx = t; idx < 64 * 128; idx += 256) {
                int n = idx >> 7, r = idx & 127;
                float sacc = b1s[n];
                sacc = fmaf(yin[r],        W1s[n],        sacc);
                sacc = fmaf(yin[128 + r],  W1s[64 + n],   sacc);
                sacc = fmaf(yin[256 + r],  W1s[128 + n],  sacc);
                sacc = fmaf(yin[384 + r],  W1s[192 + n],  sacc);
                sacc = fmaf(yin[512 + r],  W1s[256 + n],  sacc);
                bufA[n * SBUF + r] = tanh_fast(sacc);
            }
            __syncthreads();
            // ---- Layer 2: K=64 -> N=128 ----
            gemm_tanh_layer<64, 128, 8>(bufA, W2s, b2s, bufB, t);
            __syncthreads();
            // ---- Layer 3: K=128 -> N=64 (overwrites bufA) ----
            gemm_tanh_layer<128, 64, 4>(bufB, W3s, b3s, bufA, t);
            __syncthreads();
            // ---- Layer 4 + RK4 state update (one thread per row) ----
            if (t < 128) {
                float s0 = b4s[0], s1 = b4s[1], s2 = b4s[2];
#pragma unroll 8
                for (int k = 0; k < 64; ++k) {
                    float h = bufA[k * SBUF + t];
                    s0 = fmaf(h, W4s[k * 3 + 0], s0);
                    s1 = fmaf(h, W4s[k * 3 + 1], s1);
                    s2 = fmaf(h, W4s[k * 3 + 2], s2);
                }
                if (sub == 0) {
                    aS = s0; aI = s1; aR = s2;
                } else if (sub == 3) {
                    aS += s0; aI += s1; aR += s2;
                } else {
                    aS = fmaf(2.0f, s0, aS);
                    aI = fmaf(2.0f, s1, aI);
                    aR = fmaf(2.0f, s2, aR);
                }
                if (sub < 3) {
                    float cy = (sub == 2) ? dt : 0.5f * dt;
                    yin[t]        = fmaf(cy, s0, bS);
                    yin[128 + t]  = fmaf(cy, s1, bI);
                    yin[256 + t]  = fmaf(cy, s2, bR);
                } else {
                    float c = dt * (1.0f / 6.0f);
                    bS = fmaf(c, aS, bS);
                    bI = fmaf(c, aI, bI);
                    bR = fmaf(c, aR, bR);
                    yin[t]       = bS;
                    yin[128 + t] = bI;
                    yin[256 + t] = bR;
                    float m  = fmaxf(bS, fmaxf(bI, bR));
                    float e0 = __expf(bS - m), e1 = __expf(bI - m), e2 = __expf(bR - m);
                    float inv = __fdividef(1.0f, e0 + e1 + e2);
                    size_t o = ((size_t)(s + 1) * B + (b0 + t)) * 3;
                    out[o] = e0 * inv; out[o + 1] = e1 * inv; out[o + 2] = e2 * inv;
                }
            }
            __syncthreads();
        }
    }
}

extern "C" void kernel_launch(void* const* d_in, const int* in_sizes, int n_in,
                              void* d_out, int out_size) {
    const float* y0 = (const float*)d_in[0];
    const float* ts = (const float*)d_in[1];
    const float* be = (const float*)d_in[2];
    const float* ga = (const float*)d_in[3];
    const float* W1 = (const float*)d_in[4];
    const float* b1 = (const float*)d_in[5];
    const float* W2 = (const float*)d_in[6];
    const float* b2 = (const float*)d_in[7];
    const float* W3 = (const float*)d_in[8];
    const float* b3 = (const float*)d_in[9];
    const float* W4 = (const float*)d_in[10];
    const float* b4 = (const float*)d_in[11];

    int B = in_sizes[2];  // beta length
    int T = in_sizes[1];  // t_span length

    size_t smem_bytes = (size_t)SM_FLOATS * sizeof(float);
    cudaFuncSetAttribute(node_sir_kernel,
                         cudaFuncAttributeMaxDynamicSharedMemorySize,
                         (int)smem_bytes);

    node_sir_kernel<<<B / 128, 256, smem_bytes>>>(
        y0, ts, be, ga, W1, b1, W2, b2, W3, b3, W4, b4,
        (float*)d_out, B, T);
}